// round 2
// baseline (speedup 1.0000x reference)
#include <cuda_runtime.h>
#include <math.h>

#define BATCH 4
#define CCH   512
#define HW    4096

// ---------------- scratch (static __device__ — no allocation allowed) -------
__device__ float g_mean_cc[BATCH*CCH];
__device__ float g_inv_cc [BATCH*CCH];
__device__ float g_mean_ss[BATCH*CCH];
__device__ float g_inv_ss [BATCH*CCH];
__device__ float g_W1p[BATCH*CCH*CCH];
__device__ float g_b1p[BATCH*CCH];
__device__ float g_W2p[BATCH*CCH*CCH];
__device__ float g_b2p[BATCH*CCH];
__device__ float g_Q[(size_t)BATCH*HW*CCH];   // (b, pos, ch)
__device__ float g_K[(size_t)BATCH*HW*CCH];
__device__ float g_V[(size_t)BATCH*HW*CCH];
__device__ float g_O[(size_t)BATCH*HW*CCH];
__device__ float g_S[(size_t)BATCH*HW*HW];    // scores / softmax, 256 MB

// ---------------- reductions -------------------------------------------------
__device__ __forceinline__ float warpSum(float v) {
    #pragma unroll
    for (int o = 16; o > 0; o >>= 1) v += __shfl_down_sync(0xffffffffu, v, o);
    return v;
}
__device__ __forceinline__ float warpMax(float v) {
    #pragma unroll
    for (int o = 16; o > 0; o >>= 1) v = fmaxf(v, __shfl_down_sync(0xffffffffu, v, o));
    return v;
}

// ---------------- instance-norm stats ---------------------------------------
// one block per (b,c) row; unbiased variance (ddof=1) to match torch/jax ref
__global__ __launch_bounds__(256) void stats_kernel(
    const float* __restrict__ x, float* __restrict__ mean, float* __restrict__ inv)
{
    int row = blockIdx.x;                      // 0..BATCH*CCH-1
    const float* p = x + (size_t)row * HW;
    float s = 0.f, sq = 0.f;
    for (int i = threadIdx.x; i < HW; i += 256) {
        float v = p[i];
        s += v; sq += v * v;
    }
    s  = warpSum(s);
    sq = warpSum(sq);
    __shared__ float ss[8], ssq[8];
    int w = threadIdx.x >> 5, lane = threadIdx.x & 31;
    if (lane == 0) { ss[w] = s; ssq[w] = sq; }
    __syncthreads();
    if (threadIdx.x == 0) {
        float S = 0.f, SQ = 0.f;
        #pragma unroll
        for (int i = 0; i < 8; i++) { S += ss[i]; SQ += ssq[i]; }
        float m   = S / (float)HW;
        float var = (SQ - (float)HW * m * m) / (float)(HW - 1);
        mean[row] = m;
        inv[row]  = rsqrtf(var + 1e-5f);
    }
}

// ---------------- fold instance-norm into conv weights ----------------------
// W'[b][o][c] = W[o][c]*inv[b][c];  b'[b][o] = b[o] - sum_c W[o][c]*mean[b][c]*inv[b][c]
__global__ __launch_bounds__(128) void fold_kernel(
    const float* __restrict__ W, const float* __restrict__ bias,
    const float* __restrict__ mean, const float* __restrict__ inv,
    float* __restrict__ Wp, float* __restrict__ bp)
{
    int o = blockIdx.x, b = blockIdx.y;
    const float* mr = mean + b * CCH;
    const float* ir = inv  + b * CCH;
    float part = 0.f;
    for (int c = threadIdx.x; c < CCH; c += 128) {
        float w  = W[o * CCH + c];
        float iv = ir[c];
        Wp[((size_t)b * CCH + o) * CCH + c] = w * iv;
        part += w * mr[c] * iv;
    }
    part = warpSum(part);
    __shared__ float sp[4];
    int w = threadIdx.x >> 5, lane = threadIdx.x & 31;
    if (lane == 0) sp[w] = part;
    __syncthreads();
    if (threadIdx.x == 0)
        bp[b * CCH + o] = bias[o] - (sp[0] + sp[1] + sp[2] + sp[3]);
}

// ---------------- GEMM tiles: 64x64x16, 256 thr, 4x4 per thread -------------
// Q/K/V:  Out[p][o] = sum_c W[o][c] * X[c][p] + bias[o]
__global__ __launch_bounds__(256) void gemm_qkv(
    const float* __restrict__ X, const float* __restrict__ W,
    const float* __restrict__ bias, float* __restrict__ Out,
    int wStride, int bStride)
{
    int b = blockIdx.z;
    X    += (size_t)b * CCH * HW;
    W    += (size_t)b * wStride;
    bias += (size_t)b * bStride;
    Out  += (size_t)b * HW * CCH;
    int m0 = blockIdx.x * 64;          // position
    int n0 = blockIdx.y * 64;          // out channel
    __shared__ float Xs[16][68];
    __shared__ float Ws[16][68];
    int tid = threadIdx.x;
    int tx = tid & 15, ty = tid >> 4;
    int xk = tid >> 4, xm = (tid & 15) * 4;     // natural load of X (p contiguous)
    int wn = tid >> 2, wk = (tid & 3) * 4;      // transpose load of W (c contiguous)
    float acc[4][4] = {};
    for (int kt = 0; kt < CCH; kt += 16) {
        float4 xv = *reinterpret_cast<const float4*>(X + (size_t)(kt + xk) * HW + m0 + xm);
        float4 wv = *reinterpret_cast<const float4*>(W + (size_t)(n0 + wn) * CCH + kt + wk);
        *reinterpret_cast<float4*>(&Xs[xk][xm]) = xv;
        Ws[wk + 0][wn] = wv.x; Ws[wk + 1][wn] = wv.y;
        Ws[wk + 2][wn] = wv.z; Ws[wk + 3][wn] = wv.w;
        __syncthreads();
        #pragma unroll
        for (int kk = 0; kk < 16; kk++) {
            float4 rm = *reinterpret_cast<float4*>(&Xs[kk][ty * 4]);
            float4 rn = *reinterpret_cast<float4*>(&Ws[kk][tx * 4]);
            float m_[4] = {rm.x, rm.y, rm.z, rm.w};
            float n_[4] = {rn.x, rn.y, rn.z, rn.w};
            #pragma unroll
            for (int i = 0; i < 4; i++)
                #pragma unroll
                for (int j = 0; j < 4; j++) acc[i][j] += m_[i] * n_[j];
        }
        __syncthreads();
    }
    float4 bv = *reinterpret_cast<const float4*>(bias + n0 + tx * 4);
    #pragma unroll
    for (int i = 0; i < 4; i++) {
        int m = m0 + ty * 4 + i;
        float4 o = make_float4(acc[i][0] + bv.x, acc[i][1] + bv.y,
                               acc[i][2] + bv.z, acc[i][3] + bv.w);
        *reinterpret_cast<float4*>(Out + (size_t)m * CCH + n0 + tx * 4) = o;
    }
}

// scores: S[q][k] = sum_c Q[q][c]*K[k][c]   (NT, M=N=4096, K=512)
__global__ __launch_bounds__(256) void gemm_scores(
    const float* __restrict__ Q, const float* __restrict__ K, float* __restrict__ S)
{
    int b = blockIdx.z;
    Q += (size_t)b * HW * CCH;
    K += (size_t)b * HW * CCH;
    S += (size_t)b * HW * HW;
    int m0 = blockIdx.x * 64;
    int n0 = blockIdx.y * 64;
    __shared__ float As[16][68];
    __shared__ float Bs[16][68];
    int tid = threadIdx.x;
    int tx = tid & 15, ty = tid >> 4;
    int am = tid >> 2, ak = (tid & 3) * 4;
    float acc[4][4] = {};
    for (int kt = 0; kt < CCH; kt += 16) {
        float4 av = *reinterpret_cast<const float4*>(Q + (size_t)(m0 + am) * CCH + kt + ak);
        float4 bv = *reinterpret_cast<const float4*>(K + (size_t)(n0 + am) * CCH + kt + ak);
        As[ak + 0][am] = av.x; As[ak + 1][am] = av.y; As[ak + 2][am] = av.z; As[ak + 3][am] = av.w;
        Bs[ak + 0][am] = bv.x; Bs[ak + 1][am] = bv.y; Bs[ak + 2][am] = bv.z; Bs[ak + 3][am] = bv.w;
        __syncthreads();
        #pragma unroll
        for (int kk = 0; kk < 16; kk++) {
            float4 rm = *reinterpret_cast<float4*>(&As[kk][ty * 4]);
            float4 rn = *reinterpret_cast<float4*>(&Bs[kk][tx * 4]);
            float m_[4] = {rm.x, rm.y, rm.z, rm.w};
            float n_[4] = {rn.x, rn.y, rn.z, rn.w};
            #pragma unroll
            for (int i = 0; i < 4; i++)
                #pragma unroll
                for (int j = 0; j < 4; j++) acc[i][j] += m_[i] * n_[j];
        }
        __syncthreads();
    }
    #pragma unroll
    for (int i = 0; i < 4; i++) {
        int m = m0 + ty * 4 + i;
        float4 o = make_float4(acc[i][0], acc[i][1], acc[i][2], acc[i][3]);
        *reinterpret_cast<float4*>(S + (size_t)m * HW + n0 + tx * 4) = o;
    }
}

// softmax over last dim, in place; one block per row, 16 values per thread in regs
__global__ __launch_bounds__(256) void softmax_kernel(float* __restrict__ S)
{
    float* p = S + (size_t)blockIdx.x * HW;
    int tid = threadIdx.x;
    float vals[16];
    float mx = -INFINITY;
    #pragma unroll
    for (int i = 0; i < 16; i++) {
        vals[i] = p[tid + i * 256];
        mx = fmaxf(mx, vals[i]);
    }
    __shared__ float sh[8];
    int w = tid >> 5, lane = tid & 31;
    mx = warpMax(mx);
    if (lane == 0) sh[w] = mx;
    __syncthreads();
    if (w == 0) {
        float v = (lane < 8) ? sh[lane] : -INFINITY;
        v = warpMax(v);
        if (lane == 0) sh[0] = v;
    }
    __syncthreads();
    mx = sh[0];
    __syncthreads();
    float s = 0.f;
    #pragma unroll
    for (int i = 0; i < 16; i++) {
        vals[i] = expf(vals[i] - mx);
        s += vals[i];
    }
    s = warpSum(s);
    if (lane == 0) sh[w] = s;
    __syncthreads();
    if (w == 0) {
        float v = (lane < 8) ? sh[lane] : 0.f;
        v = warpSum(v);
        if (lane == 0) sh[0] = v;
    }
    __syncthreads();
    float invs = 1.f / sh[0];
    #pragma unroll
    for (int i = 0; i < 16; i++) p[tid + i * 256] = vals[i] * invs;
}

// O[q][c] = sum_k A[q][k] * V[k][c]   (NN, M=4096, N=512, K=4096)
__global__ __launch_bounds__(256) void gemm_av(
    const float* __restrict__ A, const float* __restrict__ V, float* __restrict__ O)
{
    int b = blockIdx.z;
    A += (size_t)b * HW * HW;
    V += (size_t)b * HW * CCH;
    O += (size_t)b * HW * CCH;
    int m0 = blockIdx.x * 64;
    int n0 = blockIdx.y * 64;
    __shared__ float As[16][68];
    __shared__ float Bs[16][68];
    int tid = threadIdx.x;
    int tx = tid & 15, ty = tid >> 4;
    int am = tid >> 2, ak = (tid & 3) * 4;      // transpose load of A
    int bk = tid >> 4, bn = (tid & 15) * 4;     // natural load of V
    float acc[4][4] = {};
    for (int kt = 0; kt < HW; kt += 16) {
        float4 av = *reinterpret_cast<const float4*>(A + (size_t)(m0 + am) * HW + kt + ak);
        float4 bv = *reinterpret_cast<const float4*>(V + (size_t)(kt + bk) * CCH + n0 + bn);
        As[ak + 0][am] = av.x; As[ak + 1][am] = av.y; As[ak + 2][am] = av.z; As[ak + 3][am] = av.w;
        *reinterpret_cast<float4*>(&Bs[bk][bn]) = bv;
        __syncthreads();
        #pragma unroll
        for (int kk = 0; kk < 16; kk++) {
            float4 rm = *reinterpret_cast<float4*>(&As[kk][ty * 4]);
            float4 rn = *reinterpret_cast<float4*>(&Bs[kk][tx * 4]);
            float m_[4] = {rm.x, rm.y, rm.z, rm.w};
            float n_[4] = {rn.x, rn.y, rn.z, rn.w};
            #pragma unroll
            for (int i = 0; i < 4; i++)
                #pragma unroll
                for (int j = 0; j < 4; j++) acc[i][j] += m_[i] * n_[j];
        }
        __syncthreads();
    }
    #pragma unroll
    for (int i = 0; i < 4; i++) {
        int m = m0 + ty * 4 + i;
        float4 o = make_float4(acc[i][0], acc[i][1], acc[i][2], acc[i][3]);
        *reinterpret_cast<float4*>(O + (size_t)m * CCH + n0 + tx * 4) = o;
    }
}

// out[o][p] = sum_c Wrs[o][c]*O[p][c] + brs[o] + x_fcc[o][p]  (NT, M=512, N=4096, K=512)
__global__ __launch_bounds__(256) void gemm_final(
    const float* __restrict__ Wrs, const float* __restrict__ brs,
    const float* __restrict__ O, const float* __restrict__ xfcc, float* __restrict__ out)
{
    int b = blockIdx.z;
    O    += (size_t)b * HW * CCH;
    xfcc += (size_t)b * CCH * HW;
    out  += (size_t)b * CCH * HW;
    int n0 = blockIdx.x * 64;      // position
    int m0 = blockIdx.y * 64;      // out channel
    __shared__ float As[16][68];
    __shared__ float Bs[16][68];
    int tid = threadIdx.x;
    int tx = tid & 15, ty = tid >> 4;
    int am = tid >> 2, ak = (tid & 3) * 4;
    float acc[4][4] = {};
    for (int kt = 0; kt < CCH; kt += 16) {
        float4 av = *reinterpret_cast<const float4*>(Wrs + (size_t)(m0 + am) * CCH + kt + ak);
        float4 bv = *reinterpret_cast<const float4*>(O   + (size_t)(n0 + am) * CCH + kt + ak);
        As[ak + 0][am] = av.x; As[ak + 1][am] = av.y; As[ak + 2][am] = av.z; As[ak + 3][am] = av.w;
        Bs[ak + 0][am] = bv.x; Bs[ak + 1][am] = bv.y; Bs[ak + 2][am] = bv.z; Bs[ak + 3][am] = bv.w;
        __syncthreads();
        #pragma unroll
        for (int kk = 0; kk < 16; kk++) {
            float4 rm = *reinterpret_cast<float4*>(&As[kk][ty * 4]);
            float4 rn = *reinterpret_cast<float4*>(&Bs[kk][tx * 4]);
            float m_[4] = {rm.x, rm.y, rm.z, rm.w};
            float n_[4] = {rn.x, rn.y, rn.z, rn.w};
            #pragma unroll
            for (int i = 0; i < 4; i++)
                #pragma unroll
                for (int j = 0; j < 4; j++) acc[i][j] += m_[i] * n_[j];
        }
        __syncthreads();
    }
    #pragma unroll
    for (int i = 0; i < 4; i++) {
        int m = m0 + ty * 4 + i;
        float bm = brs[m];
        float4 res = *reinterpret_cast<const float4*>(xfcc + (size_t)m * HW + n0 + tx * 4);
        float4 o = make_float4(acc[i][0] + bm + res.x, acc[i][1] + bm + res.y,
                               acc[i][2] + bm + res.z, acc[i][3] + bm + res.w);
        *reinterpret_cast<float4*>(out + (size_t)m * HW + n0 + tx * 4) = o;
    }
}

// ---------------- launch -----------------------------------------------------
extern "C" void kernel_launch(void* const* d_in, const int* in_sizes, int n_in,
                              void* d_out, int out_size)
{
    const float* x_fcc = (const float*)d_in[0];
    const float* x_fss = (const float*)d_in[1];
    const float* w1    = (const float*)d_in[2];
    const float* b1    = (const float*)d_in[3];
    const float* w2    = (const float*)d_in[4];
    const float* b2    = (const float*)d_in[5];
    const float* w3    = (const float*)d_in[6];
    const float* b3    = (const float*)d_in[7];
    const float* wrs   = (const float*)d_in[8];
    const float* brs   = (const float*)d_in[9];
    float* out = (float*)d_out;

    float *pMcc, *pIcc, *pMss, *pIss, *pW1p, *pB1p, *pW2p, *pB2p;
    float *pQ, *pK, *pV, *pO, *pS;
    cudaGetSymbolAddress((void**)&pMcc, g_mean_cc);
    cudaGetSymbolAddress((void**)&pIcc, g_inv_cc);
    cudaGetSymbolAddress((void**)&pMss, g_mean_ss);
    cudaGetSymbolAddress((void**)&pIss, g_inv_ss);
    cudaGetSymbolAddress((void**)&pW1p, g_W1p);
    cudaGetSymbolAddress((void**)&pB1p, g_b1p);
    cudaGetSymbolAddress((void**)&pW2p, g_W2p);
    cudaGetSymbolAddress((void**)&pB2p, g_b2p);
    cudaGetSymbolAddress((void**)&pQ, g_Q);
    cudaGetSymbolAddress((void**)&pK, g_K);
    cudaGetSymbolAddress((void**)&pV, g_V);
    cudaGetSymbolAddress((void**)&pO, g_O);
    cudaGetSymbolAddress((void**)&pS, g_S);

    // 1) instance-norm stats for both inputs
    stats_kernel<<<BATCH * CCH, 256>>>(x_fcc, pMcc, pIcc);
    stats_kernel<<<BATCH * CCH, 256>>>(x_fss, pMss, pIss);

    // 2) fold norm into conv weights (per batch)
    fold_kernel<<<dim3(CCH, BATCH), 128>>>(w1, b1, pMcc, pIcc, pW1p, pB1p);
    fold_kernel<<<dim3(CCH, BATCH), 128>>>(w2, b2, pMss, pIss, pW2p, pB2p);

    // 3) Q, K, V projections -> (pos, ch) layout
    gemm_qkv<<<dim3(64, 8, BATCH), 256>>>(x_fcc, pW1p, pB1p, pQ, CCH * CCH, CCH);
    gemm_qkv<<<dim3(64, 8, BATCH), 256>>>(x_fss, pW2p, pB2p, pK, CCH * CCH, CCH);
    gemm_qkv<<<dim3(64, 8, BATCH), 256>>>(x_fss, w3,   b3,   pV, 0, 0);

    // 4) scores = Q K^T
    gemm_scores<<<dim3(64, 64, BATCH), 256>>>(pQ, pK, pS);

    // 5) softmax rows (in place)
    softmax_kernel<<<BATCH * HW, 256>>>(pS);

    // 6) O = A V
    gemm_av<<<dim3(64, 8, BATCH), 256>>>(pS, pV, pO);

    // 7) final conv + bias + residual
    gemm_final<<<dim3(64, 8, BATCH), 256>>>(wrs, brs, pO, x_fcc, out);
}

// round 3
// speedup vs baseline: 1.0000x; 1.0000x over previous
#include <cuda_runtime.h>
#include <math.h>

#define BATCH 4
#define CCH   512
#define HW    4096

// ---------------- scratch (static __device__ — no allocation allowed) -------
__device__ float g_mean_cc[BATCH*CCH];
__device__ float g_inv_cc [BATCH*CCH];
__device__ float g_mean_ss[BATCH*CCH];
__device__ float g_inv_ss [BATCH*CCH];
__device__ float g_W1p[BATCH*CCH*CCH];
__device__ float g_b1p[BATCH*CCH];
__device__ float g_W2p[BATCH*CCH*CCH];
__device__ float g_b2p[BATCH*CCH];
__device__ float g_Q[(size_t)BATCH*HW*CCH];   // (b, pos, ch)
__device__ float g_K[(size_t)BATCH*HW*CCH];
__device__ float g_V[(size_t)BATCH*HW*CCH];
__device__ float g_O[(size_t)BATCH*HW*CCH];
__device__ float g_S[(size_t)BATCH*HW*HW];    // scores / softmax, 256 MB

// ---------------- reductions -------------------------------------------------
__device__ __forceinline__ float warpSum(float v) {
    #pragma unroll
    for (int o = 16; o > 0; o >>= 1) v += __shfl_down_sync(0xffffffffu, v, o);
    return v;
}
__device__ __forceinline__ float warpMax(float v) {
    #pragma unroll
    for (int o = 16; o > 0; o >>= 1) v = fmaxf(v, __shfl_down_sync(0xffffffffu, v, o));
    return v;
}

// ---------------- instance-norm stats ---------------------------------------
// one block per (b,c) row; unbiased variance (ddof=1) to match torch/jax ref
__global__ __launch_bounds__(256) void stats_kernel(
    const float* __restrict__ x, float* __restrict__ mean, float* __restrict__ inv)
{
    int row = blockIdx.x;                      // 0..BATCH*CCH-1
    const float* p = x + (size_t)row * HW;
    float s = 0.f, sq = 0.f;
    for (int i = threadIdx.x; i < HW; i += 256) {
        float v = p[i];
        s += v; sq += v * v;
    }
    s  = warpSum(s);
    sq = warpSum(sq);
    __shared__ float ss[8], ssq[8];
    int w = threadIdx.x >> 5, lane = threadIdx.x & 31;
    if (lane == 0) { ss[w] = s; ssq[w] = sq; }
    __syncthreads();
    if (threadIdx.x == 0) {
        float S = 0.f, SQ = 0.f;
        #pragma unroll
        for (int i = 0; i < 8; i++) { S += ss[i]; SQ += ssq[i]; }
        float m   = S / (float)HW;
        float var = (SQ - (float)HW * m * m) / (float)(HW - 1);
        mean[row] = m;
        inv[row]  = rsqrtf(var + 1e-5f);
    }
}

// ---------------- fold instance-norm into conv weights ----------------------
// W'[b][o][c] = W[o][c]*inv[b][c];  b'[b][o] = b[o] - sum_c W[o][c]*mean[b][c]*inv[b][c]
__global__ __launch_bounds__(128) void fold_kernel(
    const float* __restrict__ W, const float* __restrict__ bias,
    const float* __restrict__ mean, const float* __restrict__ inv,
    float* __restrict__ Wp, float* __restrict__ bp)
{
    int o = blockIdx.x, b = blockIdx.y;
    const float* mr = mean + b * CCH;
    const float* ir = inv  + b * CCH;
    float part = 0.f;
    for (int c = threadIdx.x; c < CCH; c += 128) {
        float w  = W[o * CCH + c];
        float iv = ir[c];
        Wp[((size_t)b * CCH + o) * CCH + c] = w * iv;
        part += w * mr[c] * iv;
    }
    part = warpSum(part);
    __shared__ float sp[4];
    int w = threadIdx.x >> 5, lane = threadIdx.x & 31;
    if (lane == 0) sp[w] = part;
    __syncthreads();
    if (threadIdx.x == 0)
        bp[b * CCH + o] = bias[o] - (sp[0] + sp[1] + sp[2] + sp[3]);
}

// ---------------- GEMM tiles: 64x64x16, 256 thr, 4x4 per thread -------------
// Q/K/V:  Out[p][o] = sum_c W[o][c] * X[c][p] + bias[o]
__global__ __launch_bounds__(256) void gemm_qkv(
    const float* __restrict__ X, const float* __restrict__ W,
    const float* __restrict__ bias, float* __restrict__ Out,
    int wStride, int bStride)
{
    int b = blockIdx.z;
    X    += (size_t)b * CCH * HW;
    W    += (size_t)b * wStride;
    bias += (size_t)b * bStride;
    Out  += (size_t)b * HW * CCH;
    int m0 = blockIdx.x * 64;          // position
    int n0 = blockIdx.y * 64;          // out channel
    __shared__ float Xs[16][68];
    __shared__ float Ws[16][68];
    int tid = threadIdx.x;
    int tx = tid & 15, ty = tid >> 4;
    int xk = tid >> 4, xm = (tid & 15) * 4;     // natural load of X (p contiguous)
    int wn = tid >> 2, wk = (tid & 3) * 4;      // transpose load of W (c contiguous)
    float acc[4][4] = {};
    for (int kt = 0; kt < CCH; kt += 16) {
        float4 xv = *reinterpret_cast<const float4*>(X + (size_t)(kt + xk) * HW + m0 + xm);
        float4 wv = *reinterpret_cast<const float4*>(W + (size_t)(n0 + wn) * CCH + kt + wk);
        *reinterpret_cast<float4*>(&Xs[xk][xm]) = xv;
        Ws[wk + 0][wn] = wv.x; Ws[wk + 1][wn] = wv.y;
        Ws[wk + 2][wn] = wv.z; Ws[wk + 3][wn] = wv.w;
        __syncthreads();
        #pragma unroll
        for (int kk = 0; kk < 16; kk++) {
            float4 rm = *reinterpret_cast<float4*>(&Xs[kk][ty * 4]);
            float4 rn = *reinterpret_cast<float4*>(&Ws[kk][tx * 4]);
            float m_[4] = {rm.x, rm.y, rm.z, rm.w};
            float n_[4] = {rn.x, rn.y, rn.z, rn.w};
            #pragma unroll
            for (int i = 0; i < 4; i++)
                #pragma unroll
                for (int j = 0; j < 4; j++) acc[i][j] += m_[i] * n_[j];
        }
        __syncthreads();
    }
    float4 bv = *reinterpret_cast<const float4*>(bias + n0 + tx * 4);
    #pragma unroll
    for (int i = 0; i < 4; i++) {
        int m = m0 + ty * 4 + i;
        float4 o = make_float4(acc[i][0] + bv.x, acc[i][1] + bv.y,
                               acc[i][2] + bv.z, acc[i][3] + bv.w);
        *reinterpret_cast<float4*>(Out + (size_t)m * CCH + n0 + tx * 4) = o;
    }
}

// scores: S[q][k] = sum_c Q[q][c]*K[k][c]   (NT, M=N=4096, K=512)
__global__ __launch_bounds__(256) void gemm_scores(
    const float* __restrict__ Q, const float* __restrict__ K, float* __restrict__ S)
{
    int b = blockIdx.z;
    Q += (size_t)b * HW * CCH;
    K += (size_t)b * HW * CCH;
    S += (size_t)b * HW * HW;
    int m0 = blockIdx.x * 64;
    int n0 = blockIdx.y * 64;
    __shared__ float As[16][68];
    __shared__ float Bs[16][68];
    int tid = threadIdx.x;
    int tx = tid & 15, ty = tid >> 4;
    int am = tid >> 2, ak = (tid & 3) * 4;
    float acc[4][4] = {};
    for (int kt = 0; kt < CCH; kt += 16) {
        float4 av = *reinterpret_cast<const float4*>(Q + (size_t)(m0 + am) * CCH + kt + ak);
        float4 bv = *reinterpret_cast<const float4*>(K + (size_t)(n0 + am) * CCH + kt + ak);
        As[ak + 0][am] = av.x; As[ak + 1][am] = av.y; As[ak + 2][am] = av.z; As[ak + 3][am] = av.w;
        Bs[ak + 0][am] = bv.x; Bs[ak + 1][am] = bv.y; Bs[ak + 2][am] = bv.z; Bs[ak + 3][am] = bv.w;
        __syncthreads();
        #pragma unroll
        for (int kk = 0; kk < 16; kk++) {
            float4 rm = *reinterpret_cast<float4*>(&As[kk][ty * 4]);
            float4 rn = *reinterpret_cast<float4*>(&Bs[kk][tx * 4]);
            float m_[4] = {rm.x, rm.y, rm.z, rm.w};
            float n_[4] = {rn.x, rn.y, rn.z, rn.w};
            #pragma unroll
            for (int i = 0; i < 4; i++)
                #pragma unroll
                for (int j = 0; j < 4; j++) acc[i][j] += m_[i] * n_[j];
        }
        __syncthreads();
    }
    #pragma unroll
    for (int i = 0; i < 4; i++) {
        int m = m0 + ty * 4 + i;
        float4 o = make_float4(acc[i][0], acc[i][1], acc[i][2], acc[i][3]);
        *reinterpret_cast<float4*>(S + (size_t)m * HW + n0 + tx * 4) = o;
    }
}

// softmax over last dim, in place; one block per row, 16 values per thread in regs
__global__ __launch_bounds__(256) void softmax_kernel(float* __restrict__ S)
{
    float* p = S + (size_t)blockIdx.x * HW;
    int tid = threadIdx.x;
    float vals[16];
    float mx = -INFINITY;
    #pragma unroll
    for (int i = 0; i < 16; i++) {
        vals[i] = p[tid + i * 256];
        mx = fmaxf(mx, vals[i]);
    }
    __shared__ float sh[8];
    int w = tid >> 5, lane = tid & 31;
    mx = warpMax(mx);
    if (lane == 0) sh[w] = mx;
    __syncthreads();
    if (w == 0) {
        float v = (lane < 8) ? sh[lane] : -INFINITY;
        v = warpMax(v);
        if (lane == 0) sh[0] = v;
    }
    __syncthreads();
    mx = sh[0];
    __syncthreads();
    float s = 0.f;
    #pragma unroll
    for (int i = 0; i < 16; i++) {
        vals[i] = expf(vals[i] - mx);
        s += vals[i];
    }
    s = warpSum(s);
    if (lane == 0) sh[w] = s;
    __syncthreads();
    if (w == 0) {
        float v = (lane < 8) ? sh[lane] : 0.f;
        v = warpSum(v);
        if (lane == 0) sh[0] = v;
    }
    __syncthreads();
    float invs = 1.f / sh[0];
    #pragma unroll
    for (int i = 0; i < 16; i++) p[tid + i * 256] = vals[i] * invs;
}

// O[q][c] = sum_k A[q][k] * V[k][c]   (NN, M=4096, N=512, K=4096)
__global__ __launch_bounds__(256) void gemm_av(
    const float* __restrict__ A, const float* __restrict__ V, float* __restrict__ O)
{
    int b = blockIdx.z;
    A += (size_t)b * HW * HW;
    V += (size_t)b * HW * CCH;
    O += (size_t)b * HW * CCH;
    int m0 = blockIdx.x * 64;
    int n0 = blockIdx.y * 64;
    __shared__ float As[16][68];
    __shared__ float Bs[16][68];
    int tid = threadIdx.x;
    int tx = tid & 15, ty = tid >> 4;
    int am = tid >> 2, ak = (tid & 3) * 4;      // transpose load of A
    int bk = tid >> 4, bn = (tid & 15) * 4;     // natural load of V
    float acc[4][4] = {};
    for (int kt = 0; kt < HW; kt += 16) {
        float4 av = *reinterpret_cast<const float4*>(A + (size_t)(m0 + am) * HW + kt + ak);
        float4 bv = *reinterpret_cast<const float4*>(V + (size_t)(kt + bk) * CCH + n0 + bn);
        As[ak + 0][am] = av.x; As[ak + 1][am] = av.y; As[ak + 2][am] = av.z; As[ak + 3][am] = av.w;
        *reinterpret_cast<float4*>(&Bs[bk][bn]) = bv;
        __syncthreads();
        #pragma unroll
        for (int kk = 0; kk < 16; kk++) {
            float4 rm = *reinterpret_cast<float4*>(&As[kk][ty * 4]);
            float4 rn = *reinterpret_cast<float4*>(&Bs[kk][tx * 4]);
            float m_[4] = {rm.x, rm.y, rm.z, rm.w};
            float n_[4] = {rn.x, rn.y, rn.z, rn.w};
            #pragma unroll
            for (int i = 0; i < 4; i++)
                #pragma unroll
                for (int j = 0; j < 4; j++) acc[i][j] += m_[i] * n_[j];
        }
        __syncthreads();
    }
    #pragma unroll
    for (int i = 0; i < 4; i++) {
        int m = m0 + ty * 4 + i;
        float4 o = make_float4(acc[i][0], acc[i][1], acc[i][2], acc[i][3]);
        *reinterpret_cast<float4*>(O + (size_t)m * CCH + n0 + tx * 4) = o;
    }
}

// out[o][p] = sum_c Wrs[o][c]*O[p][c] + brs[o] + x_fcc[o][p]  (NT, M=512, N=4096, K=512)
__global__ __launch_bounds__(256) void gemm_final(
    const float* __restrict__ Wrs, const float* __restrict__ brs,
    const float* __restrict__ O, const float* __restrict__ xfcc, float* __restrict__ out)
{
    int b = blockIdx.z;
    O    += (size_t)b * HW * CCH;
    xfcc += (size_t)b * CCH * HW;
    out  += (size_t)b * CCH * HW;
    int n0 = blockIdx.x * 64;      // position
    int m0 = blockIdx.y * 64;      // out channel
    __shared__ float As[16][68];
    __shared__ float Bs[16][68];
    int tid = threadIdx.x;
    int tx = tid & 15, ty = tid >> 4;
    int am = tid >> 2, ak = (tid & 3) * 4;
    float acc[4][4] = {};
    for (int kt = 0; kt < CCH; kt += 16) {
        float4 av = *reinterpret_cast<const float4*>(Wrs + (size_t)(m0 + am) * CCH + kt + ak);
        float4 bv = *reinterpret_cast<const float4*>(O   + (size_t)(n0 + am) * CCH + kt + ak);
        As[ak + 0][am] = av.x; As[ak + 1][am] = av.y; As[ak + 2][am] = av.z; As[ak + 3][am] = av.w;
        Bs[ak + 0][am] = bv.x; Bs[ak + 1][am] = bv.y; Bs[ak + 2][am] = bv.z; Bs[ak + 3][am] = bv.w;
        __syncthreads();
        #pragma unroll
        for (int kk = 0; kk < 16; kk++) {
            float4 rm = *reinterpret_cast<float4*>(&As[kk][ty * 4]);
            float4 rn = *reinterpret_cast<float4*>(&Bs[kk][tx * 4]);
            float m_[4] = {rm.x, rm.y, rm.z, rm.w};
            float n_[4] = {rn.x, rn.y, rn.z, rn.w};
            #pragma unroll
            for (int i = 0; i < 4; i++)
                #pragma unroll
                for (int j = 0; j < 4; j++) acc[i][j] += m_[i] * n_[j];
        }
        __syncthreads();
    }
    #pragma unroll
    for (int i = 0; i < 4; i++) {
        int m = m0 + ty * 4 + i;
        float bm = brs[m];
        float4 res = *reinterpret_cast<const float4*>(xfcc + (size_t)m * HW + n0 + tx * 4);
        float4 o = make_float4(acc[i][0] + bm + res.x, acc[i][1] + bm + res.y,
                               acc[i][2] + bm + res.z, acc[i][3] + bm + res.w);
        *reinterpret_cast<float4*>(out + (size_t)m * HW + n0 + tx * 4) = o;
    }
}

// ---------------- launch -----------------------------------------------------
extern "C" void kernel_launch(void* const* d_in, const int* in_sizes, int n_in,
                              void* d_out, int out_size)
{
    const float* x_fcc = (const float*)d_in[0];
    const float* x_fss = (const float*)d_in[1];
    const float* w1    = (const float*)d_in[2];
    const float* b1    = (const float*)d_in[3];
    const float* w2    = (const float*)d_in[4];
    const float* b2    = (const float*)d_in[5];
    const float* w3    = (const float*)d_in[6];
    const float* b3    = (const float*)d_in[7];
    const float* wrs   = (const float*)d_in[8];
    const float* brs   = (const float*)d_in[9];
    float* out = (float*)d_out;

    float *pMcc, *pIcc, *pMss, *pIss, *pW1p, *pB1p, *pW2p, *pB2p;
    float *pQ, *pK, *pV, *pO, *pS;
    cudaGetSymbolAddress((void**)&pMcc, g_mean_cc);
    cudaGetSymbolAddress((void**)&pIcc, g_inv_cc);
    cudaGetSymbolAddress((void**)&pMss, g_mean_ss);
    cudaGetSymbolAddress((void**)&pIss, g_inv_ss);
    cudaGetSymbolAddress((void**)&pW1p, g_W1p);
    cudaGetSymbolAddress((void**)&pB1p, g_b1p);
    cudaGetSymbolAddress((void**)&pW2p, g_W2p);
    cudaGetSymbolAddress((void**)&pB2p, g_b2p);
    cudaGetSymbolAddress((void**)&pQ, g_Q);
    cudaGetSymbolAddress((void**)&pK, g_K);
    cudaGetSymbolAddress((void**)&pV, g_V);
    cudaGetSymbolAddress((void**)&pO, g_O);
    cudaGetSymbolAddress((void**)&pS, g_S);

    // 1) instance-norm stats for both inputs
    stats_kernel<<<BATCH * CCH, 256>>>(x_fcc, pMcc, pIcc);
    stats_kernel<<<BATCH * CCH, 256>>>(x_fss, pMss, pIss);

    // 2) fold norm into conv weights (per batch)
    fold_kernel<<<dim3(CCH, BATCH), 128>>>(w1, b1, pMcc, pIcc, pW1p, pB1p);
    fold_kernel<<<dim3(CCH, BATCH), 128>>>(w2, b2, pMss, pIss, pW2p, pB2p);

    // 3) Q, K, V projections -> (pos, ch) layout
    gemm_qkv<<<dim3(64, 8, BATCH), 256>>>(x_fcc, pW1p, pB1p, pQ, CCH * CCH, CCH);
    gemm_qkv<<<dim3(64, 8, BATCH), 256>>>(x_fss, pW2p, pB2p, pK, CCH * CCH, CCH);
    gemm_qkv<<<dim3(64, 8, BATCH), 256>>>(x_fss, w3,   b3,   pV, 0, 0);

    // 4) scores = Q K^T
    gemm_scores<<<dim3(64, 64, BATCH), 256>>>(pQ, pK, pS);

    // 5) softmax rows (in place)
    softmax_kernel<<<BATCH * HW, 256>>>(pS);

    // 6) O = A V
    gemm_av<<<dim3(64, 8, BATCH), 256>>>(pS, pV, pO);

    // 7) final conv + bias + residual
    gemm_final<<<dim3(64, 8, BATCH), 256>>>(wrs, brs, pO, x_fcc, out);
}

// round 4
// speedup vs baseline: 1.0137x; 1.0136x over previous
#include <cuda_runtime.h>
#include <math.h>
#include <stdint.h>

#define BATCH 4
#define CCH   512
#define HW    4096

// ---------------- scratch (static __device__ — no allocation allowed) -------
__device__ float g_mean_cc[BATCH*CCH];
__device__ float g_inv_cc [BATCH*CCH];
__device__ float g_mean_ss[BATCH*CCH];
__device__ float g_inv_ss [BATCH*CCH];
__device__ float g_W1p[BATCH*CCH*CCH];
__device__ float g_b1p[BATCH*CCH];
__device__ float g_W2p[BATCH*CCH*CCH];
__device__ float g_b2p[BATCH*CCH];
__device__ float g_Q[(size_t)BATCH*HW*CCH];   // (b, pos, ch)
__device__ float g_K[(size_t)BATCH*HW*CCH];
__device__ float g_V[(size_t)BATCH*HW*CCH];
__device__ float g_O[(size_t)BATCH*HW*CCH];
__device__ float g_S[(size_t)BATCH*HW*HW];    // scores / softmax, 256 MB

// ---------------- reductions -------------------------------------------------
__device__ __forceinline__ float warpSum(float v) {
    #pragma unroll
    for (int o = 16; o > 0; o >>= 1) v += __shfl_down_sync(0xffffffffu, v, o);
    return v;
}
__device__ __forceinline__ float warpMax(float v) {
    #pragma unroll
    for (int o = 16; o > 0; o >>= 1) v = fmaxf(v, __shfl_down_sync(0xffffffffu, v, o));
    return v;
}

// ---------------- packed fp32x2 FMA (sm_103a FFMA2) --------------------------
__device__ __forceinline__ void ffma2(unsigned long long &d,
                                      unsigned long long a,
                                      unsigned long long b) {
    asm volatile("fma.rn.f32x2 %0, %1, %2, %0;" : "+l"(d) : "l"(a), "l"(b));
}
__device__ __forceinline__ unsigned long long dup2(float v) {
    unsigned long long r;
    unsigned u = __float_as_uint(v);
    asm volatile("mov.b64 %0, {%1, %1};" : "=l"(r) : "r"(u));
    return r;
}

// ---------------- instance-norm stats ---------------------------------------
__global__ __launch_bounds__(256) void stats_kernel(
    const float* __restrict__ x, float* __restrict__ mean, float* __restrict__ inv)
{
    int row = blockIdx.x;
    const float* p = x + (size_t)row * HW;
    float s = 0.f, sq = 0.f;
    for (int i = threadIdx.x; i < HW; i += 256) {
        float v = p[i];
        s += v; sq += v * v;
    }
    s  = warpSum(s);
    sq = warpSum(sq);
    __shared__ float ss[8], ssq[8];
    int w = threadIdx.x >> 5, lane = threadIdx.x & 31;
    if (lane == 0) { ss[w] = s; ssq[w] = sq; }
    __syncthreads();
    if (threadIdx.x == 0) {
        float S = 0.f, SQ = 0.f;
        #pragma unroll
        for (int i = 0; i < 8; i++) { S += ss[i]; SQ += ssq[i]; }
        float m   = S / (float)HW;
        float var = (SQ - (float)HW * m * m) / (float)(HW - 1);
        mean[row] = m;
        inv[row]  = rsqrtf(var + 1e-5f);
    }
}

// ---------------- fold instance-norm into conv weights ----------------------
__global__ __launch_bounds__(128) void fold_kernel(
    const float* __restrict__ W, const float* __restrict__ bias,
    const float* __restrict__ mean, const float* __restrict__ inv,
    float* __restrict__ Wp, float* __restrict__ bp)
{
    int o = blockIdx.x, b = blockIdx.y;
    const float* mr = mean + b * CCH;
    const float* ir = inv  + b * CCH;
    float part = 0.f;
    for (int c = threadIdx.x; c < CCH; c += 128) {
        float w  = W[o * CCH + c];
        float iv = ir[c];
        Wp[((size_t)b * CCH + o) * CCH + c] = w * iv;
        part += w * mr[c] * iv;
    }
    part = warpSum(part);
    __shared__ float sp[4];
    int w = threadIdx.x >> 5, lane = threadIdx.x & 31;
    if (lane == 0) sp[w] = part;
    __syncthreads();
    if (threadIdx.x == 0)
        bp[b * CCH + o] = bias[o] - (sp[0] + sp[1] + sp[2] + sp[3]);
}

// ---------------- big SGEMM: 128x128x16 tiles, 256 thr, 8x8/thr, FFMA2 -------
// TA: 0 -> A is [K][M] (m-contig, lda = row stride); 1 -> A is [M][K] (k-contig)
// TB: 0 -> B is [K][N] (n-contig);                   1 -> B is [N][K] (k-contig)
// EPI: 0 none; 1 C += bias[n]; 2 C += bias[m] + resid[m*ldc+n]
template<int TA, int TB, int EPI>
__global__ __launch_bounds__(256) void sgemm128(
    const float* __restrict__ A, const float* __restrict__ B,
    float* __restrict__ C,
    const float* __restrict__ bias, const float* __restrict__ resid,
    int Kd, int lda, int ldb, int ldc,
    size_t strideA, size_t strideB, size_t strideC,
    size_t strideBias, size_t strideResid)
{
    const int bz = blockIdx.z;
    A += strideA * bz;
    B += strideB * bz;
    C += strideC * bz;
    const float* biasP  = bias  ? bias  + strideBias  * bz : nullptr;
    const float* residP = resid ? resid + strideResid * bz : nullptr;

    const int m0 = blockIdx.y * 128;
    const int n0 = blockIdx.x * 128;

    __shared__ float As[2][16][132];
    __shared__ float Bs[2][16][132];

    const int tid = threadIdx.x;
    const int tx = tid & 15, ty = tid >> 4;

    float4 ra[2], rb[2];

    auto loadA = [&](int kt) {
        #pragma unroll
        for (int r = 0; r < 2; r++) {
            int idx = tid + 256 * r;
            if (TA == 0) {
                int k = idx >> 5, c = (idx & 31) << 2;
                ra[r] = *reinterpret_cast<const float4*>(A + (size_t)(kt + k) * lda + m0 + c);
            } else {
                int m = idx >> 2, k4 = (idx & 3) << 2;
                ra[r] = *reinterpret_cast<const float4*>(A + (size_t)(m0 + m) * lda + kt + k4);
            }
        }
    };
    auto loadB = [&](int kt) {
        #pragma unroll
        for (int r = 0; r < 2; r++) {
            int idx = tid + 256 * r;
            if (TB == 0) {
                int k = idx >> 5, c = (idx & 31) << 2;
                rb[r] = *reinterpret_cast<const float4*>(B + (size_t)(kt + k) * ldb + n0 + c);
            } else {
                int n = idx >> 2, k4 = (idx & 3) << 2;
                rb[r] = *reinterpret_cast<const float4*>(B + (size_t)(n0 + n) * ldb + kt + k4);
            }
        }
    };
    auto storeA = [&](int buf) {
        #pragma unroll
        for (int r = 0; r < 2; r++) {
            int idx = tid + 256 * r;
            if (TA == 0) {
                int k = idx >> 5, c = (idx & 31) << 2;
                *reinterpret_cast<float4*>(&As[buf][k][c]) = ra[r];
            } else {
                int m = idx >> 2, k4 = (idx & 3) << 2;
                As[buf][k4 + 0][m] = ra[r].x;
                As[buf][k4 + 1][m] = ra[r].y;
                As[buf][k4 + 2][m] = ra[r].z;
                As[buf][k4 + 3][m] = ra[r].w;
            }
        }
    };
    auto storeB = [&](int buf) {
        #pragma unroll
        for (int r = 0; r < 2; r++) {
            int idx = tid + 256 * r;
            if (TB == 0) {
                int k = idx >> 5, c = (idx & 31) << 2;
                *reinterpret_cast<float4*>(&Bs[buf][k][c]) = rb[r];
            } else {
                int n = idx >> 2, k4 = (idx & 3) << 2;
                Bs[buf][k4 + 0][n] = rb[r].x;
                Bs[buf][k4 + 1][n] = rb[r].y;
                Bs[buf][k4 + 2][n] = rb[r].z;
                Bs[buf][k4 + 3][n] = rb[r].w;
            }
        }
    };

    // acc[i][j]: fp32x2 pair covering rows m = ty*8 + 2i + {0,1}, col n = tx*8 + j
    unsigned long long acc[4][8];
    #pragma unroll
    for (int i = 0; i < 4; i++)
        #pragma unroll
        for (int j = 0; j < 8; j++) acc[i][j] = 0ull;

    const int nk = Kd >> 4;

    loadA(0); loadB(0);
    storeA(0); storeB(0);
    __syncthreads();

    for (int t = 0; t < nk; t++) {
        const int buf = t & 1;
        if (t + 1 < nk) { loadA((t + 1) << 4); loadB((t + 1) << 4); }

        #pragma unroll
        for (int kk = 0; kk < 16; kk++) {
            unsigned long long ap[4];
            #pragma unroll
            for (int i = 0; i < 4; i++)
                ap[i] = *reinterpret_cast<const unsigned long long*>(&As[buf][kk][ty * 8 + 2 * i]);
            float4 b0 = *reinterpret_cast<const float4*>(&Bs[buf][kk][tx * 8]);
            float4 b1 = *reinterpret_cast<const float4*>(&Bs[buf][kk][tx * 8 + 4]);
            float bv[8] = {b0.x, b0.y, b0.z, b0.w, b1.x, b1.y, b1.z, b1.w};
            #pragma unroll
            for (int j = 0; j < 8; j++) {
                unsigned long long bd = dup2(bv[j]);
                #pragma unroll
                for (int i = 0; i < 4; i++) ffma2(acc[i][j], ap[i], bd);
            }
        }

        if (t + 1 < nk) {
            storeA(buf ^ 1); storeB(buf ^ 1);
            __syncthreads();
        }
    }

    // epilogue
    float bn[8];
    if (EPI == 1) {
        #pragma unroll
        for (int j = 0; j < 8; j++) bn[j] = biasP[n0 + tx * 8 + j];
    }
    #pragma unroll
    for (int i = 0; i < 4; i++) {
        #pragma unroll
        for (int p = 0; p < 2; p++) {
            int m = m0 + ty * 8 + 2 * i + p;
            float v[8];
            #pragma unroll
            for (int j = 0; j < 8; j++) {
                unsigned long long u = acc[i][j];
                v[j] = __uint_as_float(p ? (unsigned)(u >> 32) : (unsigned)u);
            }
            if (EPI == 1) {
                #pragma unroll
                for (int j = 0; j < 8; j++) v[j] += bn[j];
            }
            if (EPI == 2) {
                float bm = biasP[m];
                float4 r0 = *reinterpret_cast<const float4*>(residP + (size_t)m * ldc + n0 + tx * 8);
                float4 r1 = *reinterpret_cast<const float4*>(residP + (size_t)m * ldc + n0 + tx * 8 + 4);
                v[0] += bm + r0.x; v[1] += bm + r0.y; v[2] += bm + r0.z; v[3] += bm + r0.w;
                v[4] += bm + r1.x; v[5] += bm + r1.y; v[6] += bm + r1.z; v[7] += bm + r1.w;
            }
            float4 o0 = make_float4(v[0], v[1], v[2], v[3]);
            float4 o1 = make_float4(v[4], v[5], v[6], v[7]);
            *reinterpret_cast<float4*>(C + (size_t)m * ldc + n0 + tx * 8)     = o0;
            *reinterpret_cast<float4*>(C + (size_t)m * ldc + n0 + tx * 8 + 4) = o1;
        }
    }
}

// ---------------- softmax over last dim, in place ----------------------------
__global__ __launch_bounds__(256) void softmax_kernel(float* __restrict__ S)
{
    float* p = S + (size_t)blockIdx.x * HW;
    int tid = threadIdx.x;
    float vals[16];
    float mx = -INFINITY;
    #pragma unroll
    for (int i = 0; i < 16; i++) {
        vals[i] = p[tid + i * 256];
        mx = fmaxf(mx, vals[i]);
    }
    __shared__ float sh[8];
    int w = tid >> 5, lane = tid & 31;
    mx = warpMax(mx);
    if (lane == 0) sh[w] = mx;
    __syncthreads();
    if (w == 0) {
        float v = (lane < 8) ? sh[lane] : -INFINITY;
        v = warpMax(v);
        if (lane == 0) sh[0] = v;
    }
    __syncthreads();
    mx = sh[0];
    __syncthreads();
    float s = 0.f;
    #pragma unroll
    for (int i = 0; i < 16; i++) {
        vals[i] = expf(vals[i] - mx);
        s += vals[i];
    }
    s = warpSum(s);
    if (lane == 0) sh[w] = s;
    __syncthreads();
    if (w == 0) {
        float v = (lane < 8) ? sh[lane] : 0.f;
        v = warpSum(v);
        if (lane == 0) sh[0] = v;
    }
    __syncthreads();
    float invs = 1.f / sh[0];
    #pragma unroll
    for (int i = 0; i < 16; i++) p[tid + i * 256] = vals[i] * invs;
}

// ---------------- launch -----------------------------------------------------
extern "C" void kernel_launch(void* const* d_in, const int* in_sizes, int n_in,
                              void* d_out, int out_size)
{
    const float* x_fcc = (const float*)d_in[0];
    const float* x_fss = (const float*)d_in[1];
    const float* w1    = (const float*)d_in[2];
    const float* b1    = (const float*)d_in[3];
    const float* w2    = (const float*)d_in[4];
    const float* b2    = (const float*)d_in[5];
    const float* w3    = (const float*)d_in[6];
    const float* b3    = (const float*)d_in[7];
    const float* wrs   = (const float*)d_in[8];
    const float* brs   = (const float*)d_in[9];
    float* out = (float*)d_out;

    float *pMcc, *pIcc, *pMss, *pIss, *pW1p, *pB1p, *pW2p, *pB2p;
    float *pQ, *pK, *pV, *pO, *pS;
    cudaGetSymbolAddress((void**)&pMcc, g_mean_cc);
    cudaGetSymbolAddress((void**)&pIcc, g_inv_cc);
    cudaGetSymbolAddress((void**)&pMss, g_mean_ss);
    cudaGetSymbolAddress((void**)&pIss, g_inv_ss);
    cudaGetSymbolAddress((void**)&pW1p, g_W1p);
    cudaGetSymbolAddress((void**)&pB1p, g_b1p);
    cudaGetSymbolAddress((void**)&pW2p, g_W2p);
    cudaGetSymbolAddress((void**)&pB2p, g_b2p);
    cudaGetSymbolAddress((void**)&pQ, g_Q);
    cudaGetSymbolAddress((void**)&pK, g_K);
    cudaGetSymbolAddress((void**)&pV, g_V);
    cudaGetSymbolAddress((void**)&pO, g_O);
    cudaGetSymbolAddress((void**)&pS, g_S);

    // 1) instance-norm stats
    stats_kernel<<<BATCH * CCH, 256>>>(x_fcc, pMcc, pIcc);
    stats_kernel<<<BATCH * CCH, 256>>>(x_fss, pMss, pIss);

    // 2) fold norm into conv weights
    fold_kernel<<<dim3(CCH, BATCH), 128>>>(w1, b1, pMcc, pIcc, pW1p, pB1p);
    fold_kernel<<<dim3(CCH, BATCH), 128>>>(w2, b2, pMss, pIss, pW2p, pB2p);

    // 3) Q, K, V projections: Out[p][o] = sum_c W'[o][c] X[c][p] + b'[o]
    //    A = X direct [K=C][M=HW], B = W' trans [N=C][K=C], EPI bias[n]
    {
        dim3 grid(CCH / 128, HW / 128, BATCH);
        sgemm128<0, 1, 1><<<grid, 256>>>(x_fcc, pW1p, pQ, pB1p, nullptr,
            CCH, HW, CCH, CCH,
            (size_t)CCH * HW, (size_t)CCH * CCH, (size_t)HW * CCH, CCH, 0);
        sgemm128<0, 1, 1><<<grid, 256>>>(x_fss, pW2p, pK, pB2p, nullptr,
            CCH, HW, CCH, CCH,
            (size_t)CCH * HW, (size_t)CCH * CCH, (size_t)HW * CCH, CCH, 0);
        sgemm128<0, 1, 1><<<grid, 256>>>(x_fss, w3, pV, b3, nullptr,
            CCH, HW, CCH, CCH,
            (size_t)CCH * HW, 0, (size_t)HW * CCH, 0, 0);
    }

    // 4) scores = Q K^T  (A=Q trans, B=K trans), M=N=HW, K=C
    {
        dim3 grid(HW / 128, HW / 128, BATCH);
        sgemm128<1, 1, 0><<<grid, 256>>>(pQ, pK, pS, nullptr, nullptr,
            CCH, CCH, CCH, HW,
            (size_t)HW * CCH, (size_t)HW * CCH, (size_t)HW * HW, 0, 0);
    }

    // 5) softmax rows (in place)
    softmax_kernel<<<BATCH * HW, 256>>>(pS);

    // 6) O = A V  (A=S trans [M=HW][K=HW], B=V direct [K=HW][N=C])
    {
        dim3 grid(CCH / 128, HW / 128, BATCH);
        sgemm128<1, 0, 0><<<grid, 256>>>(pS, pV, pO, nullptr, nullptr,
            HW, HW, CCH, CCH,
            (size_t)HW * HW, (size_t)HW * CCH, (size_t)HW * CCH, 0, 0);
    }

    // 7) final conv + bias + residual: out[o][p] = sum_c Wrs[o][c] O[p][c] + brs[o] + xfcc[o][p]
    //    A = Wrs trans [M=C][K=C] (no batch stride), B = O trans [N=HW][K=C], EPI 2
    {
        dim3 grid(HW / 128, CCH / 128, BATCH);
        sgemm128<1, 1, 2><<<grid, 256>>>(wrs, pO, out, brs, x_fcc,
            CCH, CCH, CCH, HW,
            0, (size_t)HW * CCH, (size_t)CCH * HW, 0, (size_t)CCH * HW);
    }
}

// round 6
// speedup vs baseline: 2.3862x; 2.3541x over previous
#include <cuda_runtime.h>
#include <cuda_bf16.h>
#include <math.h>
#include <stdint.h>

#define BATCH 4
#define CCH   512
#define HW    4096

typedef __nv_bfloat16 bf16;

// ---------------- scratch (static __device__ — no allocation allowed) -------
__device__ float g_mean_cc[BATCH*CCH];
__device__ float g_inv_cc [BATCH*CCH];
__device__ float g_mean_ss[BATCH*CCH];
__device__ float g_inv_ss [BATCH*CCH];
__device__ float g_b1p[BATCH*CCH];
__device__ float g_b2p[BATCH*CCH];

__device__ bf16 g_W1h[BATCH*CCH*CCH], g_W1l[BATCH*CCH*CCH];
__device__ bf16 g_W2h[BATCH*CCH*CCH], g_W2l[BATCH*CCH*CCH];
__device__ bf16 g_w3h[CCH*CCH],       g_w3l[CCH*CCH];
__device__ bf16 g_wrh[CCH*CCH],       g_wrl[CCH*CCH];

__device__ bf16 g_Xch[(size_t)BATCH*HW*CCH], g_Xcl[(size_t)BATCH*HW*CCH]; // x_fcc^T
__device__ bf16 g_Xsh[(size_t)BATCH*HW*CCH], g_Xsl[(size_t)BATCH*HW*CCH]; // x_fss^T
__device__ bf16 g_Qh [(size_t)BATCH*HW*CCH], g_Ql [(size_t)BATCH*HW*CCH];
__device__ bf16 g_Kh [(size_t)BATCH*HW*CCH], g_Kl [(size_t)BATCH*HW*CCH];
__device__ bf16 g_Vth[(size_t)BATCH*CCH*HW], g_Vtl[(size_t)BATCH*CCH*HW];
__device__ bf16 g_Oh [(size_t)BATCH*HW*CCH], g_Ol [(size_t)BATCH*HW*CCH];
__device__ bf16 g_Ah [(size_t)BATCH*HW*HW],  g_Al [(size_t)BATCH*HW*HW];
__device__ float g_S [(size_t)BATCH*HW*HW];   // fp32 scores (256 MB)

// ---------------- small helpers ----------------------------------------------
__device__ __forceinline__ float warpSum(float v) {
    #pragma unroll
    for (int o = 16; o > 0; o >>= 1) v += __shfl_down_sync(0xffffffffu, v, o);
    return v;
}
__device__ __forceinline__ float warpMax(float v) {
    #pragma unroll
    for (int o = 16; o > 0; o >>= 1) v = fmaxf(v, __shfl_down_sync(0xffffffffu, v, o));
    return v;
}
__device__ __forceinline__ uint32_t smem_u32(const void* p) {
    uint32_t a;
    asm("{ .reg .u64 t; cvta.to.shared.u64 t, %1; cvt.u32.u64 %0, t; }" : "=r"(a) : "l"(p));
    return a;
}
__device__ __forceinline__ void split_bf16(float v, bf16 &hi, bf16 &lo) {
    hi = __float2bfloat16_rn(v);
    lo = __float2bfloat16_rn(v - __bfloat162float(hi));
}

// ---------------- HMMA primitives (baseline PTX, no 'a' features) ------------
__device__ __forceinline__ void ldsm4(uint32_t* r, uint32_t addr) {
    asm volatile("ldmatrix.sync.aligned.m8n8.x4.shared.b16 {%0,%1,%2,%3}, [%4];"
        : "=r"(r[0]), "=r"(r[1]), "=r"(r[2]), "=r"(r[3]) : "r"(addr));
}
__device__ __forceinline__ void mma_bf16(float* c, const uint32_t* a,
                                         uint32_t b0, uint32_t b1) {
    asm volatile(
        "mma.sync.aligned.m16n8k16.row.col.f32.bf16.bf16.f32 "
        "{%0,%1,%2,%3}, {%4,%5,%6,%7}, {%8,%9}, {%0,%1,%2,%3};"
        : "+f"(c[0]), "+f"(c[1]), "+f"(c[2]), "+f"(c[3])
        : "r"(a[0]), "r"(a[1]), "r"(a[2]), "r"(a[3]), "r"(b0), "r"(b1));
}
__device__ __forceinline__ void cp16(uint32_t saddr, const void* g) {
    asm volatile("cp.async.cg.shared.global [%0], [%1], 16;"
                 :: "r"(saddr), "l"(g) : "memory");
}
#define CP_COMMIT() asm volatile("cp.async.commit_group;" ::: "memory")
#define CP_WAIT0()  asm volatile("cp.async.wait_group 0;" ::: "memory")

// ---------------- instance-norm stats ---------------------------------------
__global__ __launch_bounds__(256) void stats_kernel(
    const float* __restrict__ x, float* __restrict__ mean, float* __restrict__ inv)
{
    int row = blockIdx.x;
    const float* p = x + (size_t)row * HW;
    float s = 0.f, sq = 0.f;
    for (int i = threadIdx.x; i < HW; i += 256) { float v = p[i]; s += v; sq += v * v; }
    s = warpSum(s); sq = warpSum(sq);
    __shared__ float ss[8], ssq[8];
    int w = threadIdx.x >> 5, lane = threadIdx.x & 31;
    if (lane == 0) { ss[w] = s; ssq[w] = sq; }
    __syncthreads();
    if (threadIdx.x == 0) {
        float S = 0.f, SQ = 0.f;
        #pragma unroll
        for (int i = 0; i < 8; i++) { S += ss[i]; SQ += ssq[i]; }
        float m = S / (float)HW;
        float var = (SQ - (float)HW * m * m) / (float)(HW - 1);
        mean[row] = m;
        inv[row]  = rsqrtf(var + 1e-5f);
    }
}

// ---------------- fold inst-norm into conv weights, emit bf16 hi/lo ----------
__global__ __launch_bounds__(128) void fold_kernel(
    const float* __restrict__ W, const float* __restrict__ bias,
    const float* __restrict__ mean, const float* __restrict__ inv,
    bf16* __restrict__ Wh, bf16* __restrict__ Wl, float* __restrict__ bp)
{
    int o = blockIdx.x, b = blockIdx.y;
    const float* mr = mean + b * CCH;
    const float* ir = inv  + b * CCH;
    float part = 0.f;
    for (int c = threadIdx.x; c < CCH; c += 128) {
        float w  = W[o * CCH + c];
        float iv = ir[c];
        float wp = w * iv;
        bf16 hi, lo; split_bf16(wp, hi, lo);
        size_t idx = ((size_t)b * CCH + o) * CCH + c;
        Wh[idx] = hi; Wl[idx] = lo;
        part += w * mr[c] * iv;
    }
    part = warpSum(part);
    __shared__ float sp[4];
    int w = threadIdx.x >> 5, lane = threadIdx.x & 31;
    if (lane == 0) sp[w] = part;
    __syncthreads();
    if (threadIdx.x == 0) bp[b * CCH + o] = bias[o] - (sp[0] + sp[1] + sp[2] + sp[3]);
}

// ---------------- plain weight split -----------------------------------------
__global__ __launch_bounds__(256) void split_kernel(
    const float* __restrict__ W, bf16* __restrict__ Wh, bf16* __restrict__ Wl, int n)
{
    int i = blockIdx.x * 256 + threadIdx.x;
    if (i < n) { bf16 hi, lo; split_bf16(W[i], hi, lo); Wh[i] = hi; Wl[i] = lo; }
}

// ---------------- transpose + split: X[C][HW] -> Xt hi/lo [HW][C] ------------
__global__ __launch_bounds__(256) void transpose_split(
    const float* __restrict__ X, bf16* __restrict__ Th, bf16* __restrict__ Tl)
{
    int b = blockIdx.z;
    X  += (size_t)b * CCH * HW;
    Th += (size_t)b * HW * CCH;
    Tl += (size_t)b * HW * CCH;
    __shared__ float t[32][33];
    int p0 = blockIdx.x * 32, c0 = blockIdx.y * 32;
    int tx = threadIdx.x & 31, ty = threadIdx.x >> 5;   // 32 x 8
    #pragma unroll
    for (int j = 0; j < 4; j++) {
        int cl = ty * 4 + j;
        t[cl][tx] = X[(size_t)(c0 + cl) * HW + p0 + tx];
    }
    __syncthreads();
    #pragma unroll
    for (int j = 0; j < 4; j++) {
        int pl = ty * 4 + j;
        float v = t[tx][pl];
        bf16 hi, lo; split_bf16(v, hi, lo);
        size_t idx = (size_t)(p0 + pl) * CCH + c0 + tx;
        Th[idx] = hi; Tl[idx] = lo;
    }
}

// ---------------- HMMA NT GEMM: D = Ah Bh^T + Ah Bl^T + Al Bh^T --------------
// A: [M][K] bf16 k-contig, B: [N][K] bf16 k-contig.
// Block 128x128, 8 warps (2x4), warp tile 64x32, k-tile 32, double-buffered.
// EPI: 0 fp32 C; 1 bias[n] + bf16 hi/lo; 2 bias[m] + bf16 hi/lo;
//      3 bf16 hi/lo; 4 bias[m] + resid + fp32 C
#define KTILE 32
#define SROW  80                 // padded row stride bytes (32 bf16 + 16B pad)
#define ABYTES (128 * SROW)      // 10240 per operand tile
#define BUFBYTES (4 * ABYTES)    // Ah, Al, Bh, Bl
#define SMEMTOT (2 * BUFBYTES)   // 81920

template<int EPI>
__global__ __launch_bounds__(256) void hgemm(
    const bf16* __restrict__ Ah, const bf16* __restrict__ Al,
    const bf16* __restrict__ Bh, const bf16* __restrict__ Bl,
    int Kpass, size_t sA, size_t sB,
    float* __restrict__ C, size_t sC,
    bf16* __restrict__ Chi, bf16* __restrict__ Clo, size_t sCh,
    int ldc,
    const float* __restrict__ bias, size_t sBias,
    const float* __restrict__ resid, size_t sResid)
{
    extern __shared__ __align__(16) char smem[];
    const int tid  = threadIdx.x;
    const int wid  = tid >> 5, lane = tid & 31;
    const int wm   = wid >> 2, wn = wid & 3;      // 2 x 4 warp grid
    const int bz   = blockIdx.z;
    const int m0   = blockIdx.y * 128;
    const int n0   = blockIdx.x * 128;

    const char* gAh = (const char*)(Ah + bz * sA);
    const char* gAl = (const char*)(Al + bz * sA);
    const char* gBh = (const char*)(Bh + bz * sB);
    const char* gBl = (const char*)(Bl + bz * sB);
    const size_t rowB = (size_t)Kpass * 2;

    const uint32_t sb = smem_u32(smem);

    // per-thread gmem/smem chunk mapping: 512 chunks of 16B per operand tile
    const int ch0 = tid, ch1 = tid + 256;
    const int r0c = ch0 >> 2, c0c = (ch0 & 3) * 16;
    const int r1c = ch1 >> 2, c1c = (ch1 & 3) * 16;
    const uint32_t so0 = (uint32_t)(r0c * SROW + c0c);
    const uint32_t so1 = (uint32_t)(r1c * SROW + c1c);

    auto issue = [&](int t, int buf) {
        const size_t kb = (size_t)t * (KTILE * 2);      // byte offset along K
        const uint32_t s = sb + buf * BUFBYTES;
        const size_t ga0 = (size_t)(m0 + r0c) * rowB + kb + c0c;
        const size_t ga1 = (size_t)(m0 + r1c) * rowB + kb + c1c;
        const size_t gb0 = (size_t)(n0 + r0c) * rowB + kb + c0c;
        const size_t gb1 = (size_t)(n0 + r1c) * rowB + kb + c1c;
        cp16(s              + so0, gAh + ga0);
        cp16(s              + so1, gAh + ga1);
        cp16(s +   ABYTES   + so0, gAl + ga0);
        cp16(s +   ABYTES   + so1, gAl + ga1);
        cp16(s + 2*ABYTES   + so0, gBh + gb0);
        cp16(s + 2*ABYTES   + so1, gBh + gb1);
        cp16(s + 3*ABYTES   + so0, gBl + gb0);
        cp16(s + 3*ABYTES   + so1, gBl + gb1);
        CP_COMMIT();
    };

    float acc[4][4][4];
    #pragma unroll
    for (int i = 0; i < 4; i++)
        #pragma unroll
        for (int j = 0; j < 4; j++)
            #pragma unroll
            for (int q = 0; q < 4; q++) acc[i][j][q] = 0.f;

    const int nt = Kpass / KTILE;
    const int lr = lane & 15, lc = (lane >> 4) * 16;

    issue(0, 0);
    for (int t = 0; t < nt; t++) {
        const int buf = t & 1;
        CP_WAIT0();
        __syncthreads();
        if (t + 1 < nt) issue(t + 1, buf ^ 1);

        const uint32_t aH = sb + buf * BUFBYTES;
        const uint32_t aL = aH + ABYTES;
        const uint32_t bH = aH + 2 * ABYTES;
        const uint32_t bL = aH + 3 * ABYTES;

        #pragma unroll
        for (int ks = 0; ks < 2; ks++) {
            const int kof = ks * 32;
            uint32_t ah[4][4], al[4][4], bh[2][4], bl[2][4];
            #pragma unroll
            for (int mt = 0; mt < 4; mt++) {
                uint32_t off = (uint32_t)((wm * 64 + mt * 16 + lr) * SROW + kof + lc);
                ldsm4(ah[mt], aH + off);
                ldsm4(al[mt], aL + off);
            }
            #pragma unroll
            for (int p = 0; p < 2; p++) {
                uint32_t off = (uint32_t)((wn * 32 + p * 16 + lr) * SROW + kof + lc);
                ldsm4(bh[p], bH + off);
                ldsm4(bl[p], bL + off);
            }
            #pragma unroll
            for (int mt = 0; mt < 4; mt++) {
                #pragma unroll
                for (int ntl = 0; ntl < 4; ntl++) {
                    const int p = ntl >> 1, h = ntl & 1;
                    mma_bf16(acc[mt][ntl], ah[mt], bh[p][h], bh[p][h + 2]);
                    mma_bf16(acc[mt][ntl], ah[mt], bl[p][h], bl[p][h + 2]);
                    mma_bf16(acc[mt][ntl], al[mt], bh[p][h], bh[p][h + 2]);
                }
            }
        }
        __syncthreads();
    }

    // ---- epilogue ----
    const int n_base = n0 + wn * 32;
    const int m_base = m0 + wm * 64;
    #pragma unroll
    for (int ntl = 0; ntl < 4; ntl++) {
        const int n = n_base + ntl * 8 + 2 * (lane & 3);
        float bn0 = 0.f, bn1 = 0.f;
        if (EPI == 1) {
            bn0 = bias[bz * sBias + n];
            bn1 = bias[bz * sBias + n + 1];
        }
        #pragma unroll
        for (int mt = 0; mt < 4; mt++) {
            #pragma unroll
            for (int half = 0; half < 2; half++) {
                const int m = m_base + mt * 16 + (lane >> 2) + half * 8;
                float v0 = acc[mt][ntl][half * 2 + 0];
                float v1 = acc[mt][ntl][half * 2 + 1];
                if (EPI == 1) { v0 += bn0; v1 += bn1; }
                if (EPI == 2 || EPI == 4) {
                    float bm = bias[bz * sBias + m];
                    v0 += bm; v1 += bm;
                }
                if (EPI == 4) {
                    const float* rp = resid + bz * sResid + (size_t)m * ldc + n;
                    v0 += rp[0]; v1 += rp[1];
                }
                if (EPI == 0 || EPI == 4) {
                    float2 o = make_float2(v0, v1);
                    *(float2*)(C + bz * sC + (size_t)m * ldc + n) = o;
                } else {
                    bf16 h0, l0, h1, l1;
                    split_bf16(v0, h0, l0);
                    split_bf16(v1, h1, l1);
                    __nv_bfloat162 hp; hp.x = h0; hp.y = h1;
                    __nv_bfloat162 lp; lp.x = l0; lp.y = l1;
                    *(__nv_bfloat162*)(Chi + bz * sCh + (size_t)m * ldc + n) = hp;
                    *(__nv_bfloat162*)(Clo + bz * sCh + (size_t)m * ldc + n) = lp;
                }
            }
        }
    }
}

// ---------------- softmax: fp32 scores row -> bf16 hi/lo A -------------------
__global__ __launch_bounds__(256) void softmax_split(
    const float* __restrict__ S, bf16* __restrict__ Ah, bf16* __restrict__ Al)
{
    const float* p = S + (size_t)blockIdx.x * HW;
    bf16* ah = Ah + (size_t)blockIdx.x * HW;
    bf16* al = Al + (size_t)blockIdx.x * HW;
    int tid = threadIdx.x;
    float vals[16];
    float mx = -INFINITY;
    #pragma unroll
    for (int i = 0; i < 16; i++) { vals[i] = p[tid + i * 256]; mx = fmaxf(mx, vals[i]); }
    __shared__ float sh[8];
    int w = tid >> 5, lane = tid & 31;
    mx = warpMax(mx);
    if (lane == 0) sh[w] = mx;
    __syncthreads();
    if (w == 0) {
        float v = (lane < 8) ? sh[lane] : -INFINITY;
        v = warpMax(v);
        if (lane == 0) sh[0] = v;
    }
    __syncthreads();
    mx = sh[0];
    __syncthreads();
    float s = 0.f;
    #pragma unroll
    for (int i = 0; i < 16; i++) { vals[i] = expf(vals[i] - mx); s += vals[i]; }
    s = warpSum(s);
    if (lane == 0) sh[w] = s;
    __syncthreads();
    if (w == 0) {
        float v = (lane < 8) ? sh[lane] : 0.f;
        v = warpSum(v);
        if (lane == 0) sh[0] = v;
    }
    __syncthreads();
    float invs = 1.f / sh[0];
    #pragma unroll
    for (int i = 0; i < 16; i++) {
        float v = vals[i] * invs;
        bf16 hi, lo; split_bf16(v, hi, lo);
        ah[tid + i * 256] = hi;
        al[tid + i * 256] = lo;
    }
}

// ---------------- launch -----------------------------------------------------
extern "C" void kernel_launch(void* const* d_in, const int* in_sizes, int n_in,
                              void* d_out, int out_size)
{
    const float* x_fcc = (const float*)d_in[0];
    const float* x_fss = (const float*)d_in[1];
    const float* w1  = (const float*)d_in[2];
    const float* b1  = (const float*)d_in[3];
    const float* w2  = (const float*)d_in[4];
    const float* b2  = (const float*)d_in[5];
    const float* w3  = (const float*)d_in[6];
    const float* b3  = (const float*)d_in[7];
    const float* wrs = (const float*)d_in[8];
    const float* brs = (const float*)d_in[9];
    float* out = (float*)d_out;

    #define SYM(p, s) void* p##_; cudaGetSymbolAddress(&p##_, s); auto p = (decltype(&s[0]))p##_;
    SYM(pMcc, g_mean_cc) SYM(pIcc, g_inv_cc) SYM(pMss, g_mean_ss) SYM(pIss, g_inv_ss)
    SYM(pB1, g_b1p) SYM(pB2, g_b2p)
    SYM(pW1h, g_W1h) SYM(pW1l, g_W1l) SYM(pW2h, g_W2h) SYM(pW2l, g_W2l)
    SYM(pw3h, g_w3h) SYM(pw3l, g_w3l) SYM(pwrh, g_wrh) SYM(pwrl, g_wrl)
    SYM(pXch, g_Xch) SYM(pXcl, g_Xcl) SYM(pXsh, g_Xsh) SYM(pXsl, g_Xsl)
    SYM(pQh, g_Qh) SYM(pQl, g_Ql) SYM(pKh, g_Kh) SYM(pKl, g_Kl)
    SYM(pVth, g_Vth) SYM(pVtl, g_Vtl) SYM(pOh, g_Oh) SYM(pOl, g_Ol)
    SYM(pAh, g_Ah) SYM(pAl, g_Al) SYM(pS, g_S)
    #undef SYM

    cudaFuncSetAttribute(hgemm<0>, cudaFuncAttributeMaxDynamicSharedMemorySize, SMEMTOT);
    cudaFuncSetAttribute(hgemm<1>, cudaFuncAttributeMaxDynamicSharedMemorySize, SMEMTOT);
    cudaFuncSetAttribute(hgemm<2>, cudaFuncAttributeMaxDynamicSharedMemorySize, SMEMTOT);
    cudaFuncSetAttribute(hgemm<3>, cudaFuncAttributeMaxDynamicSharedMemorySize, SMEMTOT);
    cudaFuncSetAttribute(hgemm<4>, cudaFuncAttributeMaxDynamicSharedMemorySize, SMEMTOT);

    // 1) instance-norm stats
    stats_kernel<<<BATCH * CCH, 256>>>(x_fcc, pMcc, pIcc);
    stats_kernel<<<BATCH * CCH, 256>>>(x_fss, pMss, pIss);

    // 2) fold norm into W1/W2 (bf16 hi/lo) + bias; split w3, wrs
    fold_kernel<<<dim3(CCH, BATCH), 128>>>(w1, b1, pMcc, pIcc, pW1h, pW1l, pB1);
    fold_kernel<<<dim3(CCH, BATCH), 128>>>(w2, b2, pMss, pIss, pW2h, pW2l, pB2);
    split_kernel<<<CCH * CCH / 256, 256>>>(w3,  pw3h, pw3l, CCH * CCH);
    split_kernel<<<CCH * CCH / 256, 256>>>(wrs, pwrh, pwrl, CCH * CCH);

    // 3) transpose + split inputs: X[C][HW] -> Xt[HW][C] bf16 hi/lo
    transpose_split<<<dim3(HW / 32, CCH / 32, BATCH), 256>>>(x_fcc, pXch, pXcl);
    transpose_split<<<dim3(HW / 32, CCH / 32, BATCH), 256>>>(x_fss, pXsh, pXsl);

    const size_t sX = (size_t)HW * CCH;     // bf16 activation batch stride
    const size_t sW = (size_t)CCH * CCH;
    const size_t sS = (size_t)HW * HW;
    const size_t sV = (size_t)CCH * HW;

    // 4) Q = Xcc_t W1'^T + b1'[n]   (M=HW, N=C)
    hgemm<1><<<dim3(CCH/128, HW/128, BATCH), 256, SMEMTOT>>>(
        pXch, pXcl, pW1h, pW1l, CCH, sX, sW,
        nullptr, 0, pQh, pQl, sX, CCH, pB1, CCH, nullptr, 0);
    //    K = Xss_t W2'^T + b2'[n]
    hgemm<1><<<dim3(CCH/128, HW/128, BATCH), 256, SMEMTOT>>>(
        pXsh, pXsl, pW2h, pW2l, CCH, sX, sW,
        nullptr, 0, pKh, pKl, sX, CCH, pB2, CCH, nullptr, 0);
    //    Vt = w3 Xss_t^T + b3[m]   (M=C, N=HW) -> Vt[o][p]
    hgemm<2><<<dim3(HW/128, CCH/128, BATCH), 256, SMEMTOT>>>(
        pw3h, pw3l, pXsh, pXsl, CCH, 0, sX,
        nullptr, 0, pVth, pVtl, sV, HW, b3, 0, nullptr, 0);

    // 5) scores = Q K^T (fp32 out), M=N=HW
    hgemm<0><<<dim3(HW/128, HW/128, BATCH), 256, SMEMTOT>>>(
        pQh, pQl, pKh, pKl, CCH, sX, sX,
        pS, sS, nullptr, nullptr, 0, HW, nullptr, 0, nullptr, 0);

    // 6) softmax -> A bf16 hi/lo
    softmax_split<<<BATCH * HW, 256>>>(pS, pAh, pAl);

    // 7) O = A Vt^T (M=HW, N=C, K=HW) -> O[q][c] bf16 hi/lo
    hgemm<3><<<dim3(CCH/128, HW/128, BATCH), 256, SMEMTOT>>>(
        pAh, pAl, pVth, pVtl, HW, sS, sV,
        nullptr, 0, pOh, pOl, sX, CCH, nullptr, 0, nullptr, 0);

    // 8) out = Wrs O^T + brs[m] + x_fcc  (M=C, N=HW, fp32)
    hgemm<4><<<dim3(HW/128, CCH/128, BATCH), 256, SMEMTOT>>>(
        pwrh, pwrl, pOh, pOl, CCH, 0, sX,
        out, (size_t)CCH * HW, nullptr, nullptr, 0, HW, brs, 0, x_fcc, (size_t)CCH * HW);
}